// round 1
// baseline (speedup 1.0000x reference)
#include <cuda_runtime.h>
#include <math.h>

#define RF 129
#define NF (RF*RF*RF)
#define H 64

// ---- scratch (device globals; no allocations allowed) ----
__device__ float g_bufA[NF];
__device__ float g_bufB[NF];
__device__ float g_true[NF];
__device__ unsigned char g_calc[NF];   // "calculated" at full 129^3 lattice
__device__ unsigned char g_mA[NF];
__device__ unsigned char g_mB[NF];
__device__ unsigned char g_mC[NF];
__device__ unsigned char g_mD[NF];

// ---------------------------------------------------------------------------
// init: calculated = True at ::8,::8,::8 (the 17^3 seed lattice)
// ---------------------------------------------------------------------------
__global__ void k_init_calc() {
    int idx = blockIdx.x * blockDim.x + threadIdx.x;
    if (idx >= NF) return;
    int k = idx % RF;
    int j = (idx / RF) % RF;
    int i = idx / (RF * RF);
    g_calc[idx] = ((i & 7) == 0 && (j & 7) == 0 && (k & 7) == 0) ? 1 : 0;
}

// ---------------------------------------------------------------------------
// MLP evaluation: out[idx] = sigmoid(relu(relu(p@w1+b1)@w2+b2)@w3+b3)
// mask == nullptr -> dense. Weights staged in shared (w2 transposed).
// ---------------------------------------------------------------------------
__global__ void k_mlp(const float* __restrict__ w1, const float* __restrict__ b1,
                      const float* __restrict__ w2, const float* __restrict__ b2,
                      const float* __restrict__ w3, const float* __restrict__ b3,
                      float* __restrict__ out, const unsigned char* __restrict__ mask,
                      int R, int s) {
    __shared__ float s_w1[3 * H];
    __shared__ float s_b1[H];
    __shared__ float s_w2t[H * H];
    __shared__ float s_b2[H];
    __shared__ float s_w3[H];
    __shared__ float s_b3;

    const int n = R * R * R;
    const int idx = blockIdx.x * blockDim.x + threadIdx.x;
    bool active = (idx < n) && (mask == nullptr || mask[idx] != 0);

    // whole-block early exit BEFORE touching weights (saves L2 traffic on
    // the vast empty regions of the fine grids)
    if (__syncthreads_or(active ? 1 : 0) == 0) return;

    for (int t = threadIdx.x; t < 3 * H; t += blockDim.x) s_w1[t] = w1[t];
    for (int t = threadIdx.x; t < H; t += blockDim.x) {
        s_b1[t] = b1[t];
        s_b2[t] = b2[t];
        s_w3[t] = w3[t];
    }
    for (int t = threadIdx.x; t < H * H; t += blockDim.x) {
        int r = t / H, c = t % H;
        s_w2t[c * H + r] = w2[t];       // transpose: column c contiguous
    }
    if (threadIdx.x == 0) s_b3 = b3[0];
    __syncthreads();
    if (!active) return;

    int k = idx % R;
    int j = (idx / R) % R;
    int i = idx / (R * R);
    const float sc = 2.0f / 129.0f;
    float px = ((float)(k * s) + 0.5f) * sc - 1.0f;
    float py = ((float)(j * s) + 0.5f) * sc - 1.0f;
    float pz = ((float)(i * s) + 0.5f) * sc - 1.0f;

    float h1[H];
#pragma unroll
    for (int u = 0; u < H; u++) {
        float v = fmaf(px, s_w1[u], s_b1[u]);
        v = fmaf(py, s_w1[H + u], v);
        v = fmaf(pz, s_w1[2 * H + u], v);
        h1[u] = fmaxf(v, 0.0f);
    }

    float o = s_b3;
#pragma unroll 4
    for (int jj = 0; jj < H; jj++) {
        float acc = s_b2[jj];
        const float4* wr = reinterpret_cast<const float4*>(&s_w2t[jj * H]);
#pragma unroll
        for (int u = 0; u < H / 4; u++) {
            float4 w = wr[u];
            acc = fmaf(h1[4 * u + 0], w.x, acc);
            acc = fmaf(h1[4 * u + 1], w.y, acc);
            acc = fmaf(h1[4 * u + 2], w.z, acc);
            acc = fmaf(h1[4 * u + 3], w.w, acc);
        }
        o = fmaf(fmaxf(acc, 0.0f), s_w3[jj], o);
    }
    out[idx] = 1.0f / (1.0f + expf(-o));
}

// ---------------------------------------------------------------------------
// upsample prev (Rp^3) -> occ (R^3), R = 2*Rp-1 (exact half-step trilinear =
// mean of 2^{#odd axes} corners), plus fractional-validity mask
// ---------------------------------------------------------------------------
__global__ void k_upsample(const float* __restrict__ prev, float* __restrict__ occ,
                           unsigned char* __restrict__ frac, int R, int Rp) {
    const int n = R * R * R;
    int idx = blockIdx.x * blockDim.x + threadIdx.x;
    if (idx >= n) return;
    int k = idx % R;
    int j = (idx / R) % R;
    int i = idx / (R * R);
    int i0 = i >> 1, j0 = j >> 1, k0 = k >> 1;
    int di = i & 1, dj = j & 1, dk = k & 1;

    float sum = 0.0f;
    int pos = 0, cnt = 0;
    for (int dz = 0; dz <= di; dz++)
        for (int dy = 0; dy <= dj; dy++)
            for (int dx = 0; dx <= dk; dx++) {
                float v = prev[(i0 + dz) * Rp * Rp + (j0 + dy) * Rp + (k0 + dx)];
                sum += v;
                pos += (v > 0.5f) ? 1 : 0;
                cnt++;
            }
    occ[idx] = sum / (float)cnt;
    frac[idx] = (pos != 0 && pos != cnt) ? 1 : 0;
}

// ---------------------------------------------------------------------------
// generic 27-neighborhood dilation (SAME padding == clamped window)
// ---------------------------------------------------------------------------
__global__ void k_dilate(const unsigned char* __restrict__ in,
                         unsigned char* __restrict__ outm, int R) {
    const int n = R * R * R;
    int idx = blockIdx.x * blockDim.x + threadIdx.x;
    if (idx >= n) return;
    int k = idx % R;
    int j = (idx / R) % R;
    int i = idx / (R * R);
    int z0 = i > 0 ? i - 1 : 0, z1 = i < R - 1 ? i + 1 : R - 1;
    int y0 = j > 0 ? j - 1 : 0, y1 = j < R - 1 ? j + 1 : R - 1;
    int x0 = k > 0 ? k - 1 : 0, x1 = k < R - 1 ? k + 1 : R - 1;
    unsigned char v = 0;
    for (int z = z0; z <= z1 && !v; z++)
        for (int y = y0; y <= y1 && !v; y++)
            for (int x = x0; x <= x1; x++)
                if (in[z * R * R + y * R + x]) { v = 1; break; }
    outm[idx] = v;
}

// ---------------------------------------------------------------------------
// boundary = dilate(frac) & ~calculated[::s]
// ---------------------------------------------------------------------------
__global__ void k_boundary(const unsigned char* __restrict__ in,
                           unsigned char* __restrict__ outm, int R, int s) {
    const int n = R * R * R;
    int idx = blockIdx.x * blockDim.x + threadIdx.x;
    if (idx >= n) return;
    int k = idx % R;
    int j = (idx / R) % R;
    int i = idx / (R * R);
    int z0 = i > 0 ? i - 1 : 0, z1 = i < R - 1 ? i + 1 : R - 1;
    int y0 = j > 0 ? j - 1 : 0, y1 = j < R - 1 ? j + 1 : R - 1;
    int x0 = k > 0 ? k - 1 : 0, x1 = k < R - 1 ? k + 1 : R - 1;
    unsigned char v = 0;
    for (int z = z0; z <= z1 && !v; z++)
        for (int y = y0; y <= y1 && !v; y++)
            for (int x = x0; x <= x1; x++)
                if (in[z * R * R + y * R + x]) { v = 1; break; }
    if (v) {
        int cidx = (i * s) * RF * RF + (j * s) * RF + (k * s);
        if (g_calc[cidx]) v = 0;
    }
    outm[idx] = v;
}

// ---------------------------------------------------------------------------
// apply boundary: occ = occ_true; calc |= boundary; conflict mask
// ---------------------------------------------------------------------------
__global__ void k_apply(float* __restrict__ occ, const float* __restrict__ tru,
                        const unsigned char* __restrict__ bnd,
                        unsigned char* __restrict__ confl, int R, int s) {
    const int n = R * R * R;
    int idx = blockIdx.x * blockDim.x + threadIdx.x;
    if (idx >= n) return;
    if (bnd[idx]) {
        float oi = occ[idx];
        float ot = tru[idx];
        occ[idx] = ot;
        int k = idx % R;
        int j = (idx / R) % R;
        int i = idx / (R * R);
        g_calc[(i * s) * RF * RF + (j * s) * RF + (k * s)] = 1;
        confl[idx] = ((oi - 0.5f) * (ot - 0.5f) < 0.0f) ? 1 : 0;
    } else {
        confl[idx] = 0;
    }
}

// ---------------------------------------------------------------------------
// one conflict-propagation iteration:
//   nbr = dilate(conflictIn) & ~calc ; occ(nbr)=occ_true; calc|=nbr;
//   conflictOut = nbr & sign-flip(occ_prev(=interp), occ_true)
// ---------------------------------------------------------------------------
__global__ void k_conflict(float* __restrict__ occ, const float* __restrict__ tru,
                           const unsigned char* __restrict__ cin,
                           unsigned char* __restrict__ cout, int R, int s) {
    const int n = R * R * R;
    int idx = blockIdx.x * blockDim.x + threadIdx.x;
    if (idx >= n) return;
    int k = idx % R;
    int j = (idx / R) % R;
    int i = idx / (R * R);
    int cidx = (i * s) * RF * RF + (j * s) * RF + (k * s);
    unsigned char nbr = 0;
    if (!g_calc[cidx]) {
        int z0 = i > 0 ? i - 1 : 0, z1 = i < R - 1 ? i + 1 : R - 1;
        int y0 = j > 0 ? j - 1 : 0, y1 = j < R - 1 ? j + 1 : R - 1;
        int x0 = k > 0 ? k - 1 : 0, x1 = k < R - 1 ? k + 1 : R - 1;
        for (int z = z0; z <= z1 && !nbr; z++)
            for (int y = y0; y <= y1 && !nbr; y++)
                for (int x = x0; x <= x1; x++)
                    if (cin[z * R * R + y * R + x]) { nbr = 1; break; }
    }
    if (nbr) {
        float oi = occ[idx];
        float ot = tru[idx];
        occ[idx] = ot;
        g_calc[cidx] = 1;
        cout[idx] = ((oi - 0.5f) * (ot - 0.5f) < 0.0f) ? 1 : 0;
    } else {
        cout[idx] = 0;
    }
}

// ---------------------------------------------------------------------------
// host driver
// ---------------------------------------------------------------------------
static inline int blocks_for(int n, int t) { return (n + t - 1) / t; }

extern "C" void kernel_launch(void* const* d_in, const int* in_sizes, int n_in,
                              void* d_out, int out_size) {
    const float* w1 = (const float*)d_in[0];
    const float* b1 = (const float*)d_in[1];
    const float* w2 = (const float*)d_in[2];
    const float* b2 = (const float*)d_in[3];
    const float* w3 = (const float*)d_in[4];
    const float* b3 = (const float*)d_in[5];
    float* out = (float*)d_out;

    float *bufA, *bufB, *tru;
    unsigned char *mA, *mB, *mC, *mD;
    cudaGetSymbolAddress((void**)&bufA, g_bufA);
    cudaGetSymbolAddress((void**)&bufB, g_bufB);
    cudaGetSymbolAddress((void**)&tru, g_true);
    cudaGetSymbolAddress((void**)&mA, g_mA);
    cudaGetSymbolAddress((void**)&mB, g_mB);
    cudaGetSymbolAddress((void**)&mC, g_mC);
    cudaGetSymbolAddress((void**)&mD, g_mD);

    const int T = 256;

    // init calculated lattice
    k_init_calc<<<blocks_for(NF, T), T>>>();

    // level 0: dense 17^3 MLP
    {
        int R = 17, s = 8, n = R * R * R;
        k_mlp<<<blocks_for(n, 128), 128>>>(w1, b1, w2, b2, w3, b3,
                                           bufA, nullptr, R, s);
    }

    struct Lv { int R, Rp, s; float* prev; float* occ; };
    Lv levels[3] = {
        {33, 17, 4, bufA, bufB},
        {65, 33, 2, bufB, bufA},
        {129, 65, 1, bufA, out},
    };

    for (int L = 0; L < 3; L++) {
        int R = levels[L].R, Rp = levels[L].Rp, s = levels[L].s;
        int n = R * R * R;
        float* prev = levels[L].prev;
        float* occ = levels[L].occ;
        int gb = blocks_for(n, T);

        // occ_i + fractional mask
        k_upsample<<<gb, T>>>(prev, occ, mA, R, Rp);
        // boundary = dilate(frac) & ~calc
        k_boundary<<<gb, T>>>(mA, mB, R, s);
        // needed = dilate^2(boundary) — superset of every point whose
        // occ_true value is ever read at this level
        k_dilate<<<gb, T>>>(mB, mC, R);
        k_dilate<<<gb, T>>>(mC, mD, R);
        // masked MLP eval
        k_mlp<<<blocks_for(n, 128), 128>>>(w1, b1, w2, b2, w3, b3,
                                           tru, mD, R, s);
        // occ = where(boundary, occ_true, occ_i); calc |= boundary; conflict
        k_apply<<<gb, T>>>(occ, tru, mB, mA, R, s);
        // two conflict-propagation iterations
        k_conflict<<<gb, T>>>(occ, tru, mA, mC, R, s);
        k_conflict<<<gb, T>>>(occ, tru, mC, mA, R, s);
    }
}

// round 2
// speedup vs baseline: 1.8380x; 1.8380x over previous
#include <cuda_runtime.h>
#include <math.h>

#define RF 129
#define NF (RF*RF*RF)
#define H 64

// ---- scratch (device globals; no allocations allowed) ----
__device__ float g_bufA[NF];
__device__ float g_bufB[NF];
__device__ float g_true[NF];
__device__ unsigned char g_calc[NF];   // "calculated" at full 129^3 lattice
__device__ unsigned char g_mA[NF];
__device__ unsigned char g_mB[NF];
__device__ unsigned char g_mC[NF];
__device__ int g_wl[NF];               // worklist of active voxel indices
__device__ int g_count;                // worklist length

// ---- packed fp32x2 helpers (Blackwell FFMA2 path) ----
__device__ __forceinline__ unsigned long long pack2(float a, float b) {
    unsigned long long r;
    asm("mov.b64 %0, {%1, %2};" : "=l"(r) : "f"(a), "f"(b));
    return r;
}
__device__ __forceinline__ unsigned long long fma2(unsigned long long a,
                                                   unsigned long long b,
                                                   unsigned long long c) {
    unsigned long long r;
    asm("fma.rn.f32x2 %0, %1, %2, %3;" : "=l"(r) : "l"(a), "l"(b), "l"(c));
    return r;
}
__device__ __forceinline__ void unpack2(unsigned long long v, float& a, float& b) {
    asm("mov.b64 {%0, %1}, %2;" : "=f"(a), "=f"(b) : "l"(v));
}

// ---------------------------------------------------------------------------
// init: calculated = True at ::8,::8,::8 (the 17^3 seed lattice)
// ---------------------------------------------------------------------------
__global__ void k_init_calc() {
    int idx = blockIdx.x * blockDim.x + threadIdx.x;
    if (idx >= NF) return;
    int k = idx % RF;
    int j = (idx / RF) % RF;
    int i = idx / (RF * RF);
    g_calc[idx] = ((i & 7) == 0 && (j & 7) == 0 && (k & 7) == 0) ? 1 : 0;
}

// ---------------------------------------------------------------------------
// seed worklist with all n indices (dense level 0)
// ---------------------------------------------------------------------------
__global__ void k_seed_list(int n) {
    int idx = blockIdx.x * blockDim.x + threadIdx.x;
    if (idx < n) g_wl[idx] = idx;
    if (idx == 0) g_count = n;
}

// ---------------------------------------------------------------------------
// worklist MLP: 2 points per thread via packed fp32x2 FMA.
// out[idx] = sigmoid(relu(relu(p@w1+b1)@w2+b2)@w3+b3), exact fp32.
// ---------------------------------------------------------------------------
__global__ void k_mlp_list(const float* __restrict__ w1, const float* __restrict__ b1,
                           const float* __restrict__ w2, const float* __restrict__ b2,
                           const float* __restrict__ w3, const float* __restrict__ b3,
                           float* __restrict__ out, int R, int s) {
    __shared__ float s_w1[3 * H];
    __shared__ float s_b1[H];
    __shared__ float s_w2t[H * H];
    __shared__ float s_b2[H];
    __shared__ float s_w3[H];
    __shared__ float s_b3;

    const int count = g_count;
    const int npairs = (count + 1) >> 1;
    // whole-block early exit BEFORE weight staging
    if ((int)(blockIdx.x * blockDim.x) >= npairs) return;

    for (int t = threadIdx.x; t < 3 * H; t += blockDim.x) s_w1[t] = w1[t];
    for (int t = threadIdx.x; t < H; t += blockDim.x) {
        s_b1[t] = b1[t];
        s_b2[t] = b2[t];
        s_w3[t] = w3[t];
    }
    for (int t = threadIdx.x; t < H * H; t += blockDim.x) {
        int r = t / H, c = t % H;
        s_w2t[c * H + r] = w2[t];        // transpose: column c contiguous
    }
    if (threadIdx.x == 0) s_b3 = b3[0];
    __syncthreads();

    const int pair = blockIdx.x * blockDim.x + threadIdx.x;
    if (pair >= npairs) return;

    int ia = g_wl[2 * pair];
    int ib = (2 * pair + 1 < count) ? g_wl[2 * pair + 1] : ia;

    const float sc = 2.0f / 129.0f;
    int ka = ia % R, ja = (ia / R) % R, iia = ia / (R * R);
    int kb = ib % R, jb = (ib / R) % R, iib = ib / (R * R);
    float pxa = ((float)(ka * s) + 0.5f) * sc - 1.0f;
    float pya = ((float)(ja * s) + 0.5f) * sc - 1.0f;
    float pza = ((float)(iia * s) + 0.5f) * sc - 1.0f;
    float pxb = ((float)(kb * s) + 0.5f) * sc - 1.0f;
    float pyb = ((float)(jb * s) + 0.5f) * sc - 1.0f;
    float pzb = ((float)(iib * s) + 0.5f) * sc - 1.0f;

    // layer 1: scalar, then pack to f32x2
    unsigned long long h1p[H];
#pragma unroll
    for (int u = 0; u < H; u++) {
        float wx = s_w1[u], wy = s_w1[H + u], wz = s_w1[2 * H + u], bb = s_b1[u];
        float va = fmaf(pza, wz, fmaf(pya, wy, fmaf(pxa, wx, bb)));
        float vb = fmaf(pzb, wz, fmaf(pyb, wy, fmaf(pxb, wx, bb)));
        h1p[u] = pack2(fmaxf(va, 0.0f), fmaxf(vb, 0.0f));
    }

    // layer 2 (+ layer 3 accumulate): packed fp32x2 FMA
    float oA = s_b3, oB = s_b3;
#pragma unroll 2
    for (int jj = 0; jj < H; jj++) {
        unsigned long long acc = pack2(s_b2[jj], s_b2[jj]);
        const float4* wr = reinterpret_cast<const float4*>(&s_w2t[jj * H]);
#pragma unroll
        for (int u = 0; u < H / 4; u++) {
            float4 w = wr[u];
            acc = fma2(h1p[4 * u + 0], pack2(w.x, w.x), acc);
            acc = fma2(h1p[4 * u + 1], pack2(w.y, w.y), acc);
            acc = fma2(h1p[4 * u + 2], pack2(w.z, w.z), acc);
            acc = fma2(h1p[4 * u + 3], pack2(w.w, w.w), acc);
        }
        float a, b;
        unpack2(acc, a, b);
        float w3j = s_w3[jj];
        oA = fmaf(fmaxf(a, 0.0f), w3j, oA);
        oB = fmaf(fmaxf(b, 0.0f), w3j, oB);
    }
    out[ia] = 1.0f / (1.0f + expf(-oA));
    out[ib] = 1.0f / (1.0f + expf(-oB));
}

// ---------------------------------------------------------------------------
// upsample prev (Rp^3) -> occ (R^3), R = 2*Rp-1 (exact half-step trilinear =
// mean of 2^{#odd axes} corners), plus fractional-validity mask
// ---------------------------------------------------------------------------
__global__ void k_upsample(const float* __restrict__ prev, float* __restrict__ occ,
                           unsigned char* __restrict__ frac, int R, int Rp) {
    const int n = R * R * R;
    int idx = blockIdx.x * blockDim.x + threadIdx.x;
    if (idx >= n) return;
    int k = idx % R;
    int j = (idx / R) % R;
    int i = idx / (R * R);
    int i0 = i >> 1, j0 = j >> 1, k0 = k >> 1;
    int di = i & 1, dj = j & 1, dk = k & 1;

    float sum = 0.0f;
    int pos = 0, cnt = 0;
    for (int dz = 0; dz <= di; dz++)
        for (int dy = 0; dy <= dj; dy++)
            for (int dx = 0; dx <= dk; dx++) {
                float v = prev[(i0 + dz) * Rp * Rp + (j0 + dy) * Rp + (k0 + dx)];
                sum += v;
                pos += (v > 0.5f) ? 1 : 0;
                cnt++;
            }
    occ[idx] = sum / (float)cnt;
    frac[idx] = (pos != 0 && pos != cnt) ? 1 : 0;
}

// ---------------------------------------------------------------------------
// generic 27-neighborhood dilation (SAME padding == clamped window)
// ---------------------------------------------------------------------------
__global__ void k_dilate(const unsigned char* __restrict__ in,
                         unsigned char* __restrict__ outm, int R) {
    const int n = R * R * R;
    int idx = blockIdx.x * blockDim.x + threadIdx.x;
    if (idx >= n) return;
    int k = idx % R;
    int j = (idx / R) % R;
    int i = idx / (R * R);
    int z0 = i > 0 ? i - 1 : 0, z1 = i < R - 1 ? i + 1 : R - 1;
    int y0 = j > 0 ? j - 1 : 0, y1 = j < R - 1 ? j + 1 : R - 1;
    int x0 = k > 0 ? k - 1 : 0, x1 = k < R - 1 ? k + 1 : R - 1;
    unsigned char v = 0;
    for (int z = z0; z <= z1 && !v; z++)
        for (int y = y0; y <= y1 && !v; y++)
            for (int x = x0; x <= x1; x++)
                if (in[z * R * R + y * R + x]) { v = 1; break; }
    outm[idx] = v;
}

// ---------------------------------------------------------------------------
// dilate + append to worklist (warp-aggregated atomics)
// ---------------------------------------------------------------------------
__global__ void k_dilate_scan(const unsigned char* __restrict__ in, int R) {
    const int n = R * R * R;
    int idx = blockIdx.x * blockDim.x + threadIdx.x;
    unsigned char v = 0;
    if (idx < n) {
        int k = idx % R;
        int j = (idx / R) % R;
        int i = idx / (R * R);
        int z0 = i > 0 ? i - 1 : 0, z1 = i < R - 1 ? i + 1 : R - 1;
        int y0 = j > 0 ? j - 1 : 0, y1 = j < R - 1 ? j + 1 : R - 1;
        int x0 = k > 0 ? k - 1 : 0, x1 = k < R - 1 ? k + 1 : R - 1;
        for (int z = z0; z <= z1 && !v; z++)
            for (int y = y0; y <= y1 && !v; y++)
                for (int x = x0; x <= x1; x++)
                    if (in[z * R * R + y * R + x]) { v = 1; break; }
    }
    unsigned ballot = __ballot_sync(0xffffffffu, v != 0);
    if (v) {
        int lane = threadIdx.x & 31;
        int leader = __ffs(ballot) - 1;
        int base = 0;
        if (lane == leader) base = atomicAdd(&g_count, __popc(ballot));
        base = __shfl_sync(0xffffffffu, base, leader);
        int off = __popc(ballot & ((1u << lane) - 1u));
        g_wl[base + off] = idx;
    }
}

// ---------------------------------------------------------------------------
// boundary = dilate(frac) & ~calculated[::s]; also resets worklist counter
// ---------------------------------------------------------------------------
__global__ void k_boundary(const unsigned char* __restrict__ in,
                           unsigned char* __restrict__ outm, int R, int s) {
    const int n = R * R * R;
    int idx = blockIdx.x * blockDim.x + threadIdx.x;
    if (idx == 0) g_count = 0;       // reset before the later scan launch
    if (idx >= n) return;
    int k = idx % R;
    int j = (idx / R) % R;
    int i = idx / (R * R);
    int z0 = i > 0 ? i - 1 : 0, z1 = i < R - 1 ? i + 1 : R - 1;
    int y0 = j > 0 ? j - 1 : 0, y1 = j < R - 1 ? j + 1 : R - 1;
    int x0 = k > 0 ? k - 1 : 0, x1 = k < R - 1 ? k + 1 : R - 1;
    unsigned char v = 0;
    for (int z = z0; z <= z1 && !v; z++)
        for (int y = y0; y <= y1 && !v; y++)
            for (int x = x0; x <= x1; x++)
                if (in[z * R * R + y * R + x]) { v = 1; break; }
    if (v) {
        int cidx = (i * s) * RF * RF + (j * s) * RF + (k * s);
        if (g_calc[cidx]) v = 0;
    }
    outm[idx] = v;
}

// ---------------------------------------------------------------------------
// apply boundary: occ = occ_true; calc |= boundary; conflict mask
// ---------------------------------------------------------------------------
__global__ void k_apply(float* __restrict__ occ, const float* __restrict__ tru,
                        const unsigned char* __restrict__ bnd,
                        unsigned char* __restrict__ confl, int R, int s) {
    const int n = R * R * R;
    int idx = blockIdx.x * blockDim.x + threadIdx.x;
    if (idx >= n) return;
    if (bnd[idx]) {
        float oi = occ[idx];
        float ot = tru[idx];
        occ[idx] = ot;
        int k = idx % R;
        int j = (idx / R) % R;
        int i = idx / (R * R);
        g_calc[(i * s) * RF * RF + (j * s) * RF + (k * s)] = 1;
        confl[idx] = ((oi - 0.5f) * (ot - 0.5f) < 0.0f) ? 1 : 0;
    } else {
        confl[idx] = 0;
    }
}

// ---------------------------------------------------------------------------
// one conflict-propagation iteration
// ---------------------------------------------------------------------------
__global__ void k_conflict(float* __restrict__ occ, const float* __restrict__ tru,
                           const unsigned char* __restrict__ cin,
                           unsigned char* __restrict__ cout, int R, int s) {
    const int n = R * R * R;
    int idx = blockIdx.x * blockDim.x + threadIdx.x;
    if (idx >= n) return;
    int k = idx % R;
    int j = (idx / R) % R;
    int i = idx / (R * R);
    int cidx = (i * s) * RF * RF + (j * s) * RF + (k * s);
    unsigned char nbr = 0;
    if (!g_calc[cidx]) {
        int z0 = i > 0 ? i - 1 : 0, z1 = i < R - 1 ? i + 1 : R - 1;
        int y0 = j > 0 ? j - 1 : 0, y1 = j < R - 1 ? j + 1 : R - 1;
        int x0 = k > 0 ? k - 1 : 0, x1 = k < R - 1 ? k + 1 : R - 1;
        for (int z = z0; z <= z1 && !nbr; z++)
            for (int y = y0; y <= y1 && !nbr; y++)
                for (int x = x0; x <= x1; x++)
                    if (cin[z * R * R + y * R + x]) { nbr = 1; break; }
    }
    if (nbr) {
        float oi = occ[idx];
        float ot = tru[idx];
        occ[idx] = ot;
        g_calc[cidx] = 1;
        cout[idx] = ((oi - 0.5f) * (ot - 0.5f) < 0.0f) ? 1 : 0;
    } else {
        cout[idx] = 0;
    }
}

// ---------------------------------------------------------------------------
// host driver
// ---------------------------------------------------------------------------
static inline int blocks_for(int n, int t) { return (n + t - 1) / t; }

extern "C" void kernel_launch(void* const* d_in, const int* in_sizes, int n_in,
                              void* d_out, int out_size) {
    const float* w1 = (const float*)d_in[0];
    const float* b1 = (const float*)d_in[1];
    const float* w2 = (const float*)d_in[2];
    const float* b2 = (const float*)d_in[3];
    const float* w3 = (const float*)d_in[4];
    const float* b3 = (const float*)d_in[5];
    float* out = (float*)d_out;

    float *bufA, *bufB, *tru;
    unsigned char *mA, *mB, *mC;
    cudaGetSymbolAddress((void**)&bufA, g_bufA);
    cudaGetSymbolAddress((void**)&bufB, g_bufB);
    cudaGetSymbolAddress((void**)&tru, g_true);
    cudaGetSymbolAddress((void**)&mA, g_mA);
    cudaGetSymbolAddress((void**)&mB, g_mB);
    cudaGetSymbolAddress((void**)&mC, g_mC);

    const int T = 256;
    const int MT = 128;   // MLP block size

    k_init_calc<<<blocks_for(NF, T), T>>>();

    // level 0: dense 17^3 via seeded worklist
    {
        int R = 17, s = 8, n = R * R * R;
        k_seed_list<<<blocks_for(n, T), T>>>(n);
        int mp = (n + 1) / 2;
        k_mlp_list<<<blocks_for(mp, MT), MT>>>(w1, b1, w2, b2, w3, b3, bufA, R, s);
    }

    struct Lv { int R, Rp, s; float* prev; float* occ; };
    Lv levels[3] = {
        {33, 17, 4, bufA, bufB},
        {65, 33, 2, bufB, bufA},
        {129, 65, 1, bufA, out},
    };

    for (int L = 0; L < 3; L++) {
        int R = levels[L].R, Rp = levels[L].Rp, s = levels[L].s;
        int n = R * R * R;
        float* prev = levels[L].prev;
        float* occ = levels[L].occ;
        int gb = blocks_for(n, T);

        // occ_i + fractional mask
        k_upsample<<<gb, T>>>(prev, occ, mA, R, Rp);
        // boundary = dilate(frac) & ~calc  (also resets worklist counter)
        k_boundary<<<gb, T>>>(mA, mB, R, s);
        // needed = dilate^2(boundary); second dilation feeds the worklist
        k_dilate<<<gb, T>>>(mB, mC, R);
        k_dilate_scan<<<gb, T>>>(mC, R);
        // worklist MLP eval (blocks beyond worklist exit immediately)
        int mp = (n + 1) / 2;
        k_mlp_list<<<blocks_for(mp, MT), MT>>>(w1, b1, w2, b2, w3, b3, tru, R, s);
        // occ = where(boundary, occ_true, occ_i); calc |= boundary; conflict
        k_apply<<<gb, T>>>(occ, tru, mB, mA, R, s);
        // two conflict-propagation iterations
        k_conflict<<<gb, T>>>(occ, tru, mA, mC, R, s);
        k_conflict<<<gb, T>>>(occ, tru, mC, mA, R, s);
    }
}

// round 3
// speedup vs baseline: 1.8421x; 1.0022x over previous
#include <cuda_runtime.h>
#include <math.h>

#define RF 129
#define NF (RF*RF*RF)
#define H 64

// ---- scratch (device globals; no allocations allowed) ----
__device__ float g_bufA[NF];
__device__ float g_bufB[NF];
__device__ float g_true[NF];
__device__ unsigned char g_calc[NF];   // "calculated" at full 129^3 lattice
__device__ unsigned char g_mA[NF];
__device__ unsigned char g_mB[NF];
__device__ unsigned char g_mC[NF];
__device__ int g_wl[NF];               // worklist of active voxel indices
__device__ int g_count;                // worklist length

// ---- packed fp32x2 helpers (Blackwell FFMA2 path) ----
__device__ __forceinline__ unsigned long long pack2(float a, float b) {
    unsigned long long r;
    asm("mov.b64 %0, {%1, %2};" : "=l"(r) : "f"(a), "f"(b));
    return r;
}
__device__ __forceinline__ unsigned long long fma2(unsigned long long a,
                                                   unsigned long long b,
                                                   unsigned long long c) {
    unsigned long long r;
    asm("fma.rn.f32x2 %0, %1, %2, %3;" : "=l"(r) : "l"(a), "l"(b), "l"(c));
    return r;
}
__device__ __forceinline__ void unpack2(unsigned long long v, float& a, float& b) {
    asm("mov.b64 {%0, %1}, %2;" : "=f"(a), "=f"(b) : "l"(v));
}

// ---------------------------------------------------------------------------
// init: calculated = True at ::8,::8,::8 (the 17^3 seed lattice)
// ---------------------------------------------------------------------------
__global__ void k_init_calc() {
    int idx = blockIdx.x * blockDim.x + threadIdx.x;
    if (idx >= NF) return;
    int k = idx % RF;
    int j = (idx / RF) % RF;
    int i = idx / (RF * RF);
    g_calc[idx] = ((i & 7) == 0 && (j & 7) == 0 && (k & 7) == 0) ? 1 : 0;
}

// ---------------------------------------------------------------------------
// seed worklist with all n indices (dense level 0)
// ---------------------------------------------------------------------------
__global__ void k_seed_list(int n) {
    int idx = blockIdx.x * blockDim.x + threadIdx.x;
    if (idx < n) g_wl[idx] = idx;
    if (idx == 0) g_count = n;
}

// ---------------------------------------------------------------------------
// worklist MLP: 2 points per thread via packed fp32x2 FMA.
// out[idx] = sigmoid(relu(relu(p@w1+b1)@w2+b2)@w3+b3), exact fp32.
// ---------------------------------------------------------------------------
__global__ void k_mlp_list(const float* __restrict__ w1, const float* __restrict__ b1,
                           const float* __restrict__ w2, const float* __restrict__ b2,
                           const float* __restrict__ w3, const float* __restrict__ b3,
                           float* __restrict__ out, int R, int s) {
    __shared__ float s_w1[3 * H];
    __shared__ float s_b1[H];
    __shared__ float s_w2t[H * H];
    __shared__ float s_b2[H];
    __shared__ float s_w3[H];
    __shared__ float s_b3;

    const int count = g_count;
    const int npairs = (count + 1) >> 1;
    // whole-block early exit BEFORE weight staging
    if ((int)(blockIdx.x * blockDim.x) >= npairs) return;

    for (int t = threadIdx.x; t < 3 * H; t += blockDim.x) s_w1[t] = w1[t];
    for (int t = threadIdx.x; t < H; t += blockDim.x) {
        s_b1[t] = b1[t];
        s_b2[t] = b2[t];
        s_w3[t] = w3[t];
    }
    for (int t = threadIdx.x; t < H * H; t += blockDim.x) {
        int r = t / H, c = t % H;
        s_w2t[c * H + r] = w2[t];        // transpose: column c contiguous
    }
    if (threadIdx.x == 0) s_b3 = b3[0];
    __syncthreads();

    const int pair = blockIdx.x * blockDim.x + threadIdx.x;
    if (pair >= npairs) return;

    int ia = g_wl[2 * pair];
    int ib = (2 * pair + 1 < count) ? g_wl[2 * pair + 1] : ia;

    const float sc = 2.0f / 129.0f;
    int ka = ia % R, ja = (ia / R) % R, iia = ia / (R * R);
    int kb = ib % R, jb = (ib / R) % R, iib = ib / (R * R);
    float pxa = ((float)(ka * s) + 0.5f) * sc - 1.0f;
    float pya = ((float)(ja * s) + 0.5f) * sc - 1.0f;
    float pza = ((float)(iia * s) + 0.5f) * sc - 1.0f;
    float pxb = ((float)(kb * s) + 0.5f) * sc - 1.0f;
    float pyb = ((float)(jb * s) + 0.5f) * sc - 1.0f;
    float pzb = ((float)(iib * s) + 0.5f) * sc - 1.0f;

    // layer 1: scalar, then pack to f32x2
    unsigned long long h1p[H];
#pragma unroll
    for (int u = 0; u < H; u++) {
        float wx = s_w1[u], wy = s_w1[H + u], wz = s_w1[2 * H + u], bb = s_b1[u];
        float va = fmaf(pza, wz, fmaf(pya, wy, fmaf(pxa, wx, bb)));
        float vb = fmaf(pzb, wz, fmaf(pyb, wy, fmaf(pxb, wx, bb)));
        h1p[u] = pack2(fmaxf(va, 0.0f), fmaxf(vb, 0.0f));
    }

    // layer 2 (+ layer 3 accumulate): packed fp32x2 FMA
    float oA = s_b3, oB = s_b3;
#pragma unroll 2
    for (int jj = 0; jj < H; jj++) {
        unsigned long long acc = pack2(s_b2[jj], s_b2[jj]);
        const float4* wr = reinterpret_cast<const float4*>(&s_w2t[jj * H]);
#pragma unroll
        for (int u = 0; u < H / 4; u++) {
            float4 w = wr[u];
            acc = fma2(h1p[4 * u + 0], pack2(w.x, w.x), acc);
            acc = fma2(h1p[4 * u + 1], pack2(w.y, w.y), acc);
            acc = fma2(h1p[4 * u + 2], pack2(w.z, w.z), acc);
            acc = fma2(h1p[4 * u + 3], pack2(w.w, w.w), acc);
        }
        float a, b;
        unpack2(acc, a, b);
        float w3j = s_w3[jj];
        oA = fmaf(fmaxf(a, 0.0f), w3j, oA);
        oB = fmaf(fmaxf(b, 0.0f), w3j, oB);
    }
    out[ia] = 1.0f / (1.0f + expf(-oA));
    out[ib] = 1.0f / (1.0f + expf(-oB));
}

// ---------------------------------------------------------------------------
// upsample prev (Rp^3) -> occ (R^3), R = 2*Rp-1 (exact half-step trilinear =
// mean of 2^{#odd axes} corners), plus fractional-validity mask
// ---------------------------------------------------------------------------
__global__ void k_upsample(const float* __restrict__ prev, float* __restrict__ occ,
                           unsigned char* __restrict__ frac, int R, int Rp) {
    const int n = R * R * R;
    int idx = blockIdx.x * blockDim.x + threadIdx.x;
    if (idx >= n) return;
    int k = idx % R;
    int j = (idx / R) % R;
    int i = idx / (R * R);
    int i0 = i >> 1, j0 = j >> 1, k0 = k >> 1;
    int di = i & 1, dj = j & 1, dk = k & 1;

    float sum = 0.0f;
    int pos = 0, cnt = 0;
    for (int dz = 0; dz <= di; dz++)
        for (int dy = 0; dy <= dj; dy++)
            for (int dx = 0; dx <= dk; dx++) {
                float v = prev[(i0 + dz) * Rp * Rp + (j0 + dy) * Rp + (k0 + dx)];
                sum += v;
                pos += (v > 0.5f) ? 1 : 0;
                cnt++;
            }
    occ[idx] = sum / (float)cnt;
    frac[idx] = (pos != 0 && pos != cnt) ? 1 : 0;
}

// ---------------------------------------------------------------------------
// generic 27-neighborhood dilation (SAME padding == clamped window)
// ---------------------------------------------------------------------------
__global__ void k_dilate(const unsigned char* __restrict__ in,
                         unsigned char* __restrict__ outm, int R) {
    const int n = R * R * R;
    int idx = blockIdx.x * blockDim.x + threadIdx.x;
    if (idx >= n) return;
    int k = idx % R;
    int j = (idx / R) % R;
    int i = idx / (R * R);
    int z0 = i > 0 ? i - 1 : 0, z1 = i < R - 1 ? i + 1 : R - 1;
    int y0 = j > 0 ? j - 1 : 0, y1 = j < R - 1 ? j + 1 : R - 1;
    int x0 = k > 0 ? k - 1 : 0, x1 = k < R - 1 ? k + 1 : R - 1;
    unsigned char v = 0;
    for (int z = z0; z <= z1 && !v; z++)
        for (int y = y0; y <= y1 && !v; y++)
            for (int x = x0; x <= x1; x++)
                if (in[z * R * R + y * R + x]) { v = 1; break; }
    outm[idx] = v;
}

// ---------------------------------------------------------------------------
// dilate + append to worklist (warp-aggregated atomics)
// ---------------------------------------------------------------------------
__global__ void k_dilate_scan(const unsigned char* __restrict__ in, int R) {
    const int n = R * R * R;
    int idx = blockIdx.x * blockDim.x + threadIdx.x;
    unsigned char v = 0;
    if (idx < n) {
        int k = idx % R;
        int j = (idx / R) % R;
        int i = idx / (R * R);
        int z0 = i > 0 ? i - 1 : 0, z1 = i < R - 1 ? i + 1 : R - 1;
        int y0 = j > 0 ? j - 1 : 0, y1 = j < R - 1 ? j + 1 : R - 1;
        int x0 = k > 0 ? k - 1 : 0, x1 = k < R - 1 ? k + 1 : R - 1;
        for (int z = z0; z <= z1 && !v; z++)
            for (int y = y0; y <= y1 && !v; y++)
                for (int x = x0; x <= x1; x++)
                    if (in[z * R * R + y * R + x]) { v = 1; break; }
    }
    unsigned ballot = __ballot_sync(0xffffffffu, v != 0);
    if (v) {
        int lane = threadIdx.x & 31;
        int leader = __ffs(ballot) - 1;
        int base = 0;
        if (lane == leader) base = atomicAdd(&g_count, __popc(ballot));
        base = __shfl_sync(0xffffffffu, base, leader);
        int off = __popc(ballot & ((1u << lane) - 1u));
        g_wl[base + off] = idx;
    }
}

// ---------------------------------------------------------------------------
// boundary = dilate(frac) & ~calculated[::s]; also resets worklist counter
// ---------------------------------------------------------------------------
__global__ void k_boundary(const unsigned char* __restrict__ in,
                           unsigned char* __restrict__ outm, int R, int s) {
    const int n = R * R * R;
    int idx = blockIdx.x * blockDim.x + threadIdx.x;
    if (idx == 0) g_count = 0;       // reset before the later scan launch
    if (idx >= n) return;
    int k = idx % R;
    int j = (idx / R) % R;
    int i = idx / (R * R);
    int z0 = i > 0 ? i - 1 : 0, z1 = i < R - 1 ? i + 1 : R - 1;
    int y0 = j > 0 ? j - 1 : 0, y1 = j < R - 1 ? j + 1 : R - 1;
    int x0 = k > 0 ? k - 1 : 0, x1 = k < R - 1 ? k + 1 : R - 1;
    unsigned char v = 0;
    for (int z = z0; z <= z1 && !v; z++)
        for (int y = y0; y <= y1 && !v; y++)
            for (int x = x0; x <= x1; x++)
                if (in[z * R * R + y * R + x]) { v = 1; break; }
    if (v) {
        int cidx = (i * s) * RF * RF + (j * s) * RF + (k * s);
        if (g_calc[cidx]) v = 0;
    }
    outm[idx] = v;
}

// ---------------------------------------------------------------------------
// apply boundary: occ = occ_true; calc |= boundary; conflict mask
// ---------------------------------------------------------------------------
__global__ void k_apply(float* __restrict__ occ, const float* __restrict__ tru,
                        const unsigned char* __restrict__ bnd,
                        unsigned char* __restrict__ confl, int R, int s) {
    const int n = R * R * R;
    int idx = blockIdx.x * blockDim.x + threadIdx.x;
    if (idx >= n) return;
    if (bnd[idx]) {
        float oi = occ[idx];
        float ot = tru[idx];
        occ[idx] = ot;
        int k = idx % R;
        int j = (idx / R) % R;
        int i = idx / (R * R);
        g_calc[(i * s) * RF * RF + (j * s) * RF + (k * s)] = 1;
        confl[idx] = ((oi - 0.5f) * (ot - 0.5f) < 0.0f) ? 1 : 0;
    } else {
        confl[idx] = 0;
    }
}

// ---------------------------------------------------------------------------
// one conflict-propagation iteration
// ---------------------------------------------------------------------------
__global__ void k_conflict(float* __restrict__ occ, const float* __restrict__ tru,
                           const unsigned char* __restrict__ cin,
                           unsigned char* __restrict__ cout, int R, int s) {
    const int n = R * R * R;
    int idx = blockIdx.x * blockDim.x + threadIdx.x;
    if (idx >= n) return;
    int k = idx % R;
    int j = (idx / R) % R;
    int i = idx / (R * R);
    int cidx = (i * s) * RF * RF + (j * s) * RF + (k * s);
    unsigned char nbr = 0;
    if (!g_calc[cidx]) {
        int z0 = i > 0 ? i - 1 : 0, z1 = i < R - 1 ? i + 1 : R - 1;
        int y0 = j > 0 ? j - 1 : 0, y1 = j < R - 1 ? j + 1 : R - 1;
        int x0 = k > 0 ? k - 1 : 0, x1 = k < R - 1 ? k + 1 : R - 1;
        for (int z = z0; z <= z1 && !nbr; z++)
            for (int y = y0; y <= y1 && !nbr; y++)
                for (int x = x0; x <= x1; x++)
                    if (cin[z * R * R + y * R + x]) { nbr = 1; break; }
    }
    if (nbr) {
        float oi = occ[idx];
        float ot = tru[idx];
        occ[idx] = ot;
        g_calc[cidx] = 1;
        cout[idx] = ((oi - 0.5f) * (ot - 0.5f) < 0.0f) ? 1 : 0;
    } else {
        cout[idx] = 0;
    }
}

// ---------------------------------------------------------------------------
// host driver
// ---------------------------------------------------------------------------
static inline int blocks_for(int n, int t) { return (n + t - 1) / t; }

extern "C" void kernel_launch(void* const* d_in, const int* in_sizes, int n_in,
                              void* d_out, int out_size) {
    const float* w1 = (const float*)d_in[0];
    const float* b1 = (const float*)d_in[1];
    const float* w2 = (const float*)d_in[2];
    const float* b2 = (const float*)d_in[3];
    const float* w3 = (const float*)d_in[4];
    const float* b3 = (const float*)d_in[5];
    float* out = (float*)d_out;

    float *bufA, *bufB, *tru;
    unsigned char *mA, *mB, *mC;
    cudaGetSymbolAddress((void**)&bufA, g_bufA);
    cudaGetSymbolAddress((void**)&bufB, g_bufB);
    cudaGetSymbolAddress((void**)&tru, g_true);
    cudaGetSymbolAddress((void**)&mA, g_mA);
    cudaGetSymbolAddress((void**)&mB, g_mB);
    cudaGetSymbolAddress((void**)&mC, g_mC);

    const int T = 256;
    const int MT = 128;   // MLP block size

    k_init_calc<<<blocks_for(NF, T), T>>>();

    // level 0: dense 17^3 via seeded worklist
    {
        int R = 17, s = 8, n = R * R * R;
        k_seed_list<<<blocks_for(n, T), T>>>(n);
        int mp = (n + 1) / 2;
        k_mlp_list<<<blocks_for(mp, MT), MT>>>(w1, b1, w2, b2, w3, b3, bufA, R, s);
    }

    struct Lv { int R, Rp, s; float* prev; float* occ; };
    Lv levels[3] = {
        {33, 17, 4, bufA, bufB},
        {65, 33, 2, bufB, bufA},
        {129, 65, 1, bufA, out},
    };

    for (int L = 0; L < 3; L++) {
        int R = levels[L].R, Rp = levels[L].Rp, s = levels[L].s;
        int n = R * R * R;
        float* prev = levels[L].prev;
        float* occ = levels[L].occ;
        int gb = blocks_for(n, T);

        // occ_i + fractional mask
        k_upsample<<<gb, T>>>(prev, occ, mA, R, Rp);
        // boundary = dilate(frac) & ~calc  (also resets worklist counter)
        k_boundary<<<gb, T>>>(mA, mB, R, s);
        // needed = dilate^2(boundary); second dilation feeds the worklist
        k_dilate<<<gb, T>>>(mB, mC, R);
        k_dilate_scan<<<gb, T>>>(mC, R);
        // worklist MLP eval (blocks beyond worklist exit immediately)
        int mp = (n + 1) / 2;
        k_mlp_list<<<blocks_for(mp, MT), MT>>>(w1, b1, w2, b2, w3, b3, tru, R, s);
        // occ = where(boundary, occ_true, occ_i); calc |= boundary; conflict
        k_apply<<<gb, T>>>(occ, tru, mB, mA, R, s);
        // two conflict-propagation iterations
        k_conflict<<<gb, T>>>(occ, tru, mA, mC, R, s);
        k_conflict<<<gb, T>>>(occ, tru, mC, mA, R, s);
    }
}